// round 10
// baseline (speedup 1.0000x reference)
#include <cuda_runtime.h>
#include <cstdint>
#include <cstdio>

#define NB   2
#define NN   50000
#define HH   64
#define NE   1000000
#define NOBS 128
#define NA   18
#define NAFF 512
#define NEFF 256
#define PB   196

#define NBLK   148
#define NW     16
#define WTOT   (NBLK * NW)     // 2368 warps
#define GROUP  4
#define WIN    512             // idx window (ints) per warp

// chunk split: NN = WTOT*21 + 272  ->  first 272 warps take 22 nodes
#define CHUNK_BIG   22
#define CHUNK_SMALL 21
#define NBIG        (NN - WTOT * CHUNK_SMALL)   // 272

typedef unsigned int u32;
typedef unsigned long long ull;

// ---------------- device scratch ----------------
__device__ float g_Wp[128 * 128];             // fused weight, [k/2][c][2] pair layout
__device__ float g_projG[NB * HH];
__device__ float g_projC[NB * HH];
__device__ int   g_flag[NN];
__device__ int   g_cnt[NN];
__device__ int   g_off[NN + 1];
__device__ int   g_cur[NN];
__device__ int   g_esrc[NE + WIN];            // padded for cp.async overread
__device__ int   g_part[256];

// ---------------- helpers ----------------
__device__ __forceinline__ void fma2(ull& d, ull a, ull b) {
    asm("fma.rn.f32x2 %0, %1, %2, %0;" : "+l"(d) : "l"(a), "l"(b));
}
__device__ __forceinline__ ull pack2(float a, float b) {
    ull r;
    asm("mov.b64 %0, {%1, %2};" : "=l"(r) : "r"(__float_as_uint(a)), "r"(__float_as_uint(b)));
    return r;
}
__device__ __forceinline__ float2 u2f2(ull v) {
    float2 f;
    f.x = __uint_as_float((unsigned)v);
    f.y = __uint_as_float((unsigned)(v >> 32));
    return f;
}
__device__ __forceinline__ void cpa16(void* dst, const void* src) {
    unsigned d = (unsigned)__cvta_generic_to_shared(dst);
    asm volatile("cp.async.cg.shared.global [%0], [%1], 16;" :: "r"(d), "l"(src));
}
__device__ __forceinline__ int warp_incl_scan(int v) {
    int lane = threadIdx.x & 31;
#pragma unroll
    for (int d = 1; d < 32; d <<= 1) {
        int t = __shfl_up_sync(0xffffffffu, v, d);
        if (lane >= d) v += t;
    }
    return v;
}
__device__ __forceinline__ float sigm(float x) { return __fdividef(1.f, 1.f + __expf(-x)); }
__device__ __forceinline__ float tanha(float x) { return 1.f - __fdividef(2.f, __expf(2.f * x) + 1.f); }

// ---------------- K1: merged prep (small proj + fused weight) ----------------
__global__ void prep_kernel(const float* __restrict__ obs,
                            const float* __restrict__ W_in,
                            const float* __restrict__ b_in,
                            const float* __restrict__ W_msg,
                            const float* __restrict__ W_gate,
                            const float* __restrict__ W_cand,
                            const int* __restrict__ afferent_idx) {
    if (blockIdx.x == 128) {
        __shared__ float proj[NB * HH];
        int t = threadIdx.x;            // 128 threads
        int b = t >> 6, h = t & 63;
        float acc = b_in[h];
        for (int o = 0; o < NOBS; o++)
            acc += obs[b * NOBS + o] * W_in[o * HH + h];
        proj[b * HH + h] = acc;
        __syncthreads();
        float ag = 0.f, ac = 0.f;
        for (int k = 0; k < HH; k++) {
            float p = proj[b * HH + k];
            ag += p * W_gate[(HH + k) * HH + h];
            ac += p * W_cand[(HH + k) * HH + h];
        }
        g_projG[b * HH + h] = ag;
        g_projC[b * HH + h] = ac;
        for (int i = t; i < NAFF; i += 128)
            g_flag[afferent_idx[i]] = 1;
    } else {
        int c = blockIdx.x;     // output column 0..127
        int k = threadIdx.x;    // input row 0..127
        float w;
        if (k < HH) {
            w = (c < HH) ? W_gate[k * HH + c] : W_cand[k * HH + (c - HH)];
        } else {
            int km = k - HH;
            float acc = 0.f;
            if (c < HH) {
                for (int t = 0; t < HH; t++)
                    acc += W_msg[km * HH + t] * W_gate[(HH + t) * HH + c];
            } else {
                for (int t = 0; t < HH; t++)
                    acc += W_msg[km * HH + t] * W_cand[(HH + t) * HH + (c - HH)];
            }
            w = acc;
        }
        // pair layout: g_Wp viewed as ull[64][128]: element (k/2, c) = {w(k_even,c), w(k_odd,c)}
        g_Wp[(k >> 1) * 256 + c * 2 + (k & 1)] = w;
    }
}

// ---------------- CSR build ----------------
__global__ void hist_kernel(const int4* __restrict__ dst4) {
    int i = (blockIdx.x * blockDim.x + threadIdx.x) * 2;
    if (i < NE / 4) {
        int4 d0 = __ldg(dst4 + i);
        int4 d1 = __ldg(dst4 + i + 1);
        atomicAdd(&g_cnt[d0.x], 1);
        atomicAdd(&g_cnt[d0.y], 1);
        atomicAdd(&g_cnt[d0.z], 1);
        atomicAdd(&g_cnt[d0.w], 1);
        atomicAdd(&g_cnt[d1.x], 1);
        atomicAdd(&g_cnt[d1.y], 1);
        atomicAdd(&g_cnt[d1.z], 1);
        atomicAdd(&g_cnt[d1.w], 1);
    }
}

__global__ void scan_part_kernel() {
    int i = blockIdx.x * 256 + threadIdx.x;
    int v = (i < NN) ? g_cnt[i] : 0;
    __shared__ int ws[8];
    int s = v;
#pragma unroll
    for (int d = 16; d > 0; d >>= 1) s += __shfl_down_sync(0xffffffffu, s, d);
    if ((threadIdx.x & 31) == 0) ws[threadIdx.x >> 5] = s;
    __syncthreads();
    if (threadIdx.x == 0) {
        int tot = 0;
        for (int w = 0; w < 8; w++) tot += ws[w];
        g_part[blockIdx.x] = tot;
    }
}

__global__ void scan_final_kernel() {      // grid PB, 256 thr; folds mid-scan in
    int i = blockIdx.x * 256 + threadIdx.x;
    int t = threadIdx.x;
    int lane = t & 31, w = t >> 5;
    __shared__ int ws[8];
    __shared__ int blockBase;

    // block base = sum of g_part[j] for j < blockIdx.x
    int pv = (t < PB && t < blockIdx.x) ? g_part[t] : 0;
#pragma unroll
    for (int d = 16; d > 0; d >>= 1) pv += __shfl_down_sync(0xffffffffu, pv, d);
    if (lane == 0) ws[w] = pv;
    __syncthreads();
    if (t == 0) {
        int s = 0;
        for (int x = 0; x < 8; x++) s += ws[x];
        blockBase = s;
    }
    __syncthreads();

    int v = (i < NN) ? g_cnt[i] : 0;
    int inc = warp_incl_scan(v);
    if (lane == 31) ws[w] = inc;
    __syncthreads();
    if (w == 0) {
        int q = (lane < 8) ? ws[lane] : 0;
        int qi = warp_incl_scan(q);
        if (lane < 8) ws[lane] = qi;
    }
    __syncthreads();
    int base = (w > 0) ? ws[w - 1] : 0;
    int off = blockBase + base + inc - v;
    if (i < NN) { g_off[i] = off; g_cur[i] = off; }
    if (i == 0) g_off[NN] = NE;
}

__global__ void scatter_kernel(const int4* __restrict__ src4,
                               const int4* __restrict__ dst4) {
    int i = (blockIdx.x * blockDim.x + threadIdx.x) * 2;
    if (i < NE / 4) {
        int4 s0 = __ldg(src4 + i);
        int4 d0 = __ldg(dst4 + i);
        int4 s1 = __ldg(src4 + i + 1);
        int4 d1 = __ldg(dst4 + i + 1);
        g_esrc[atomicAdd(&g_cur[d0.x], 1)] = s0.x;
        g_esrc[atomicAdd(&g_cur[d0.y], 1)] = s0.y;
        g_esrc[atomicAdd(&g_cur[d0.z], 1)] = s0.z;
        g_esrc[atomicAdd(&g_cur[d0.w], 1)] = s0.w;
        g_esrc[atomicAdd(&g_cur[d1.x], 1)] = s1.x;
        g_esrc[atomicAdd(&g_cur[d1.y], 1)] = s1.y;
        g_esrc[atomicAdd(&g_cur[d1.z], 1)] = s1.z;
        g_esrc[atomicAdd(&g_cur[d1.w], 1)] = s1.w;
    }
}

// ---------------- K2: fused gather + k-paired f32x2 GEMM + GRU epilogue ----------------
// f32x2 lanes hold (even-k, odd-k) partial sums: multiplier pairs {w[k],w[k+1]}
// come straight from smem (no splat MOVs); x pairs {x[k],x[k+1]} are the natural
// row layout. One lo+hi FADD per accumulator at the end.
// x row layout per node (128 ull): [b0 state(32) | b0 agg(32) | b1 state(32) | b1 agg(32)]
__global__ void __launch_bounds__(512, 1) fused_kernel(const float* __restrict__ state,
                                                       const float* __restrict__ b_gate,
                                                       const float* __restrict__ b_cand,
                                                       float* __restrict__ out_ns) {
    extern __shared__ float smem[];
    float* Ws = smem;                                    // 16384 floats ([k/2][c] ull pairs)
    ull* xs = (ull*)(smem + 16384);                      // NW * GROUP * 128 ull
    int* sIdx = (int*)(xs + NW * GROUP * 128);           // NW * WIN ints

    int tid = threadIdx.x;
    for (int i = tid; i < 4096; i += 512)
        ((float4*)Ws)[i] = ((const float4*)g_Wp)[i];
    __syncthreads();

    int warp = tid >> 5, lane = tid & 31;
    int q = lane & 15;
    int cc0 = q * 4;
    bool zside = lane < 16;

    float bias[4], pj0[4], pj1[4];
#pragma unroll
    for (int c = 0; c < 4; c++) {
        int cc = cc0 + c;
        if (zside) { bias[c] = __ldg(b_gate + cc); pj0[c] = g_projG[cc]; pj1[c] = g_projG[64 + cc]; }
        else       { bias[c] = __ldg(b_cand + cc); pj0[c] = g_projC[cc]; pj1[c] = g_projC[64 + cc]; }
    }

    ull* mx = xs + warp * (GROUP * 128);
    int* widx = sIdx + warp * WIN;
    int gwid = blockIdx.x * NW + warp;
    const float2* s0 = (const float2*)state;
    const float2* s1 = s0 + (size_t)NN * 32;
    const ull* WsU = (const ull*)Ws;
    int c0 = lane * 4;          // global output col base (0..124)

    int cBase, cCnt;
    if (gwid < NBIG) { cBase = gwid * CHUNK_BIG; cCnt = CHUNK_BIG; }
    else             { cBase = NBIG * CHUNK_BIG + (gwid - NBIG) * CHUNK_SMALL; cCnt = CHUNK_SMALL; }
    int nEnd = cBase + cCnt;

    // stage index window for the chunk
    int slab = __ldg(&g_off[cBase]) & ~3;
    for (int c = lane; c < WIN / 4; c += 32)
        cpa16(widx + c * 4, g_esrc + slab + c * 4);
    asm volatile("cp.async.commit_group;" ::: "memory");
    asm volatile("cp.async.wait_group 0;" ::: "memory");
    __syncwarp();

    int sg = 1 + (gwid % GROUP);       // staggered first sub-group size
    int n0 = cBase;
    while (n0 < nEnd) {
        int cnt = nEnd - n0;
        if (cnt > sg) cnt = sg;
        sg = GROUP;
        int flg[GROUP];

        // ---- gather phase ----
        for (int m = 0; m < cnt; m++) {
            int n = n0 + m;
            int beg = __ldg(&g_off[n]), end = __ldg(&g_off[n + 1]);
            flg[m] = __ldg(&g_flag[n]);
            float4 acc = make_float4(0.f, 0.f, 0.f, 0.f);
            int j = beg;
            while (j < end) {
                if (j >= slab + WIN) {           // refill window (rare)
                    slab = j & ~3;
                    for (int c = lane; c < WIN / 4; c += 32)
                        cpa16(widx + c * 4, g_esrc + slab + c * 4);
                    asm volatile("cp.async.commit_group;" ::: "memory");
                    asm volatile("cp.async.wait_group 0;" ::: "memory");
                    __syncwarp();
                }
                int lim = slab + WIN;
                if (lim > end) lim = end;
                for (; j + 8 <= lim; j += 8) {
                    int e[8];
#pragma unroll
                    for (int u = 0; u < 8; u++) e[u] = widx[j - slab + u];
                    float2 av[8], bv[8];
#pragma unroll
                    for (int u = 0; u < 8; u++) {
                        av[u] = __ldg(s0 + (size_t)e[u] * 32 + lane);
                        bv[u] = __ldg(s1 + (size_t)e[u] * 32 + lane);
                    }
#pragma unroll
                    for (int u = 0; u < 8; u++) {
                        acc.x += av[u].x; acc.y += av[u].y;
                        acc.z += bv[u].x; acc.w += bv[u].y;
                    }
                }
                for (; j < lim; j++) {
                    int e0 = widx[j - slab];
                    float2 a = __ldg(s0 + (size_t)e0 * 32 + lane);
                    float2 b = __ldg(s1 + (size_t)e0 * 32 + lane);
                    acc.x += a.x; acc.y += a.y; acc.z += b.x; acc.w += b.y;
                }
            }
            float2 sa = __ldg(s0 + (size_t)n * 32 + lane);
            float2 sb = __ldg(s1 + (size_t)n * 32 + lane);
            ull* row = mx + m * 128;
            row[lane]      = pack2(sa.x, sa.y);       // b0 state k=2l,2l+1
            row[32 + lane] = pack2(acc.x, acc.y);     // b0 agg  k=64+2l
            row[64 + lane] = pack2(sb.x, sb.y);       // b1 state
            row[96 + lane] = pack2(acc.z, acc.w);     // b1 agg
        }
        __syncwarp();

        // ---- FMA phase: acc[m][c][b] pairs over (even k, odd k) ----
        ull acc6[GROUP][4][2];
#pragma unroll
        for (int m = 0; m < GROUP; m++)
#pragma unroll
            for (int c = 0; c < 4; c++) { acc6[m][c][0] = 0ull; acc6[m][c][1] = 0ull; }

        const ull* r0 = mx;
        const ull* r1 = mx + 128;
        const ull* r2 = mx + 256;
        const ull* r3 = mx + 384;

#pragma unroll 2
        for (int ki = 0; ki < 64; ki++) {
            ulonglong2 w01 = *(const ulonglong2*)(WsU + ki * 128 + c0);      // cols c0, c0+1
            ulonglong2 w23 = *(const ulonglong2*)(WsU + ki * 128 + c0 + 2);  // cols c0+2, c0+3
            ull x00 = r0[ki], x01 = r0[64 + ki];
            ull x10 = r1[ki], x11 = r1[64 + ki];
            ull x20 = r2[ki], x21 = r2[64 + ki];
            ull x30 = r3[ki], x31 = r3[64 + ki];
            fma2(acc6[0][0][0], w01.x, x00); fma2(acc6[0][0][1], w01.x, x01);
            fma2(acc6[0][1][0], w01.y, x00); fma2(acc6[0][1][1], w01.y, x01);
            fma2(acc6[0][2][0], w23.x, x00); fma2(acc6[0][2][1], w23.x, x01);
            fma2(acc6[0][3][0], w23.y, x00); fma2(acc6[0][3][1], w23.y, x01);
            fma2(acc6[1][0][0], w01.x, x10); fma2(acc6[1][0][1], w01.x, x11);
            fma2(acc6[1][1][0], w01.y, x10); fma2(acc6[1][1][1], w01.y, x11);
            fma2(acc6[1][2][0], w23.x, x10); fma2(acc6[1][2][1], w23.x, x11);
            fma2(acc6[1][3][0], w23.y, x10); fma2(acc6[1][3][1], w23.y, x11);
            fma2(acc6[2][0][0], w01.x, x20); fma2(acc6[2][0][1], w01.x, x21);
            fma2(acc6[2][1][0], w01.y, x20); fma2(acc6[2][1][1], w01.y, x21);
            fma2(acc6[2][2][0], w23.x, x20); fma2(acc6[2][2][1], w23.x, x21);
            fma2(acc6[2][3][0], w23.y, x20); fma2(acc6[2][3][1], w23.y, x21);
            fma2(acc6[3][0][0], w01.x, x30); fma2(acc6[3][0][1], w01.x, x31);
            fma2(acc6[3][1][0], w01.y, x30); fma2(acc6[3][1][1], w01.y, x31);
            fma2(acc6[3][2][0], w23.x, x30); fma2(acc6[3][2][1], w23.x, x31);
            fma2(acc6[3][3][0], w23.y, x30); fma2(acc6[3][3][1], w23.y, x31);
        }

        // ---- epilogue ----
        for (int m = 0; m < cnt; m++) {
            int n = n0 + m;
            const ull* rowm = mx + m * 128;
            ull actp[4];
#pragma unroll
            for (int c = 0; c < 4; c++) {
                float2 e0 = u2f2(acc6[m][c][0]);
                float2 e1 = u2f2(acc6[m][c][1]);
                float p0 = (e0.x + e0.y) + bias[c] + (flg[m] ? pj0[c] : 0.f);
                float p1 = (e1.x + e1.y) + bias[c] + (flg[m] ? pj1[c] : 0.f);
                float a0, a1;
                if (zside) { a0 = sigm(p0);  a1 = sigm(p1); }
                else       { a0 = tanha(p0); a1 = tanha(p1); }
                actp[c] = pack2(a0, a1);
            }
            ull oth[4];
#pragma unroll
            for (int c = 0; c < 4; c++)
                oth[c] = __shfl_xor_sync(0xffffffffu, actp[c], 16);
            if (zside) {
                // state cols cc0..cc0+3, both batches
                ulonglong2 sp0 = *(const ulonglong2*)(rowm + (cc0 >> 1));        // b0
                ulonglong2 sp1 = *(const ulonglong2*)(rowm + 64 + (cc0 >> 1));   // b1
                float s0v[4], s1v[4];
                { float2 t0 = u2f2(sp0.x), t1 = u2f2(sp0.y);
                  s0v[0] = t0.x; s0v[1] = t0.y; s0v[2] = t1.x; s0v[3] = t1.y; }
                { float2 t0 = u2f2(sp1.x), t1 = u2f2(sp1.y);
                  s1v[0] = t0.x; s1v[1] = t0.y; s1v[2] = t1.x; s1v[3] = t1.y; }
                float4 o0, o1;
                float* q0 = (float*)&o0;
                float* q1 = (float*)&o1;
#pragma unroll
                for (int c = 0; c < 4; c++) {
                    float2 z = u2f2(actp[c]);     // (b0, b1) gate
                    float2 t = u2f2(oth[c]);      // (b0, b1) cand
                    q0[c] = fmaf(z.x, t.x - s0v[c], s0v[c]);
                    q1[c] = fmaf(z.y, t.y - s1v[c], s1v[c]);
                }
                *((float4*)(out_ns + (size_t)n * 64 + cc0)) = o0;
                *((float4*)(out_ns + ((size_t)NN + n) * 64 + cc0)) = o1;
            }
        }
        __syncwarp();
        n0 += cnt;
    }
}

// ---------------- K4: readout + policy heads ----------------
__global__ void readout_kernel(const float* __restrict__ ns,
                               const int* __restrict__ efferent_idx,
                               const float* __restrict__ W_dec,
                               const float* __restrict__ b_dec,
                               const float* __restrict__ W_mean,
                               const float* __restrict__ b_mean,
                               const float* __restrict__ W_ls,
                               const float* __restrict__ b_ls,
                               float* __restrict__ out) {
    __shared__ float ro[NB * HH];
    __shared__ float dec[NB * HH];
    int t = threadIdx.x;
    int b = t >> 6, h = t & 63;
    float sum = 0.f;
    for (int i = 0; i < NEFF; i++) {
        int idx = efferent_idx[i];
        sum += ns[((size_t)b * NN + idx) * HH + h];
    }
    ro[b * HH + h] = sum * (1.f / NEFF);
    __syncthreads();
    float acc = b_dec[h];
    for (int k = 0; k < HH; k++)
        acc += ro[b * HH + k] * W_dec[k * HH + h];
    dec[b * HH + h] = tanhf(acc);
    __syncthreads();
    if (t < NB * NA) {
        int bb = t / NA, a = t % NA;
        float m = b_mean[a], ls = b_ls[a];
        for (int k = 0; k < HH; k++) {
            float d = dec[bb * HH + k];
            m  += d * W_mean[k * NA + a];
            ls += d * W_ls[k * NA + a];
        }
        ls = fminf(fmaxf(ls, -5.f), 2.f);
        out[bb * NA + a] = m;
        out[NB * NA + bb * NA + a] = ls;
    }
}

// ---------------- launch ----------------
extern "C" void kernel_launch(void* const* d_in, const int* in_sizes, int n_in,
                              void* d_out, int out_size) {
    const float* obs    = (const float*)d_in[0];
    const float* state  = (const float*)d_in[1];
    const float* W_in   = (const float*)d_in[2];
    const float* b_in   = (const float*)d_in[3];
    const float* W_msg  = (const float*)d_in[4];
    const float* W_gate = (const float*)d_in[5];
    const float* b_gate = (const float*)d_in[6];
    const float* W_cand = (const float*)d_in[7];
    const float* b_cand = (const float*)d_in[8];
    const float* W_dec  = (const float*)d_in[9];
    const float* b_dec  = (const float*)d_in[10];
    const float* W_mean = (const float*)d_in[11];
    const float* b_mean = (const float*)d_in[12];
    const float* W_ls   = (const float*)d_in[13];
    const float* b_ls   = (const float*)d_in[14];
    const int* src_idx  = (const int*)d_in[15];
    const int* dst_idx  = (const int*)d_in[16];
    const int* aff_idx  = (const int*)d_in[17];
    const int* eff_idx  = (const int*)d_in[18];
    float* out = (float*)d_out;
    float* out_ns = out + 2 * NB * NA;

    void *cntp = nullptr, *flagp = nullptr;
    cudaGetSymbolAddress(&cntp, g_cnt);
    cudaGetSymbolAddress(&flagp, g_flag);
    cudaMemsetAsync(cntp, 0, sizeof(int) * NN);
    cudaMemsetAsync(flagp, 0, sizeof(int) * NN);

    prep_kernel<<<129, 128>>>(obs, W_in, b_in, W_msg, W_gate, W_cand, aff_idx);

    hist_kernel<<<(NE / 8 + 255) / 256, 256>>>((const int4*)dst_idx);
    scan_part_kernel<<<PB, 256>>>();
    scan_final_kernel<<<PB, 256>>>();
    scatter_kernel<<<(NE / 8 + 255) / 256, 256>>>((const int4*)src_idx, (const int4*)dst_idx);

    size_t smem = 16384u * 4 + (size_t)NW * GROUP * 128 * 8 + (size_t)NW * WIN * 4;  // 163840
    cudaFuncSetAttribute(fused_kernel, cudaFuncAttributeMaxDynamicSharedMemorySize, (int)smem);
    fused_kernel<<<NBLK, 512, smem>>>(state, b_gate, b_cand, out_ns);

    readout_kernel<<<1, 128>>>(out_ns, eff_idx, W_dec, b_dec, W_mean, b_mean, W_ls, b_ls, out);
}

// round 11
// speedup vs baseline: 1.2070x; 1.2070x over previous
#include <cuda_runtime.h>
#include <cstdint>
#include <cstdio>

#define NB   2
#define NN   50000
#define HH   64
#define NE   1000000
#define NOBS 128
#define NA   18
#define NAFF 512
#define NEFF 256
#define PB   196

#define NBLK   148
#define NW     16
#define WTOT   (NBLK * NW)     // 2368 warps
#define GROUP  6
#define WIN    512             // idx window (ints) per warp

// chunk split: NN = WTOT*21 + 272  ->  first 272 warps take 22 nodes
#define CHUNK_BIG   22
#define CHUNK_SMALL 21
#define NBIG        (NN - WTOT * CHUNK_SMALL)   // 272

typedef unsigned int u32;
typedef unsigned long long ull;

// ---------------- device scratch ----------------
__device__ float g_Wp[128 * 128];             // fused weight [k][c]
__device__ float g_projG[NB * HH];
__device__ float g_projC[NB * HH];
__device__ int   g_flag[NN];
__device__ int   g_cnt[NN];
__device__ int   g_off[NN + 1];
__device__ int   g_cur[NN];
__device__ int   g_esrc[NE + WIN];            // padded for cp.async overread
__device__ int   g_part[256];

// ---------------- helpers ----------------
__device__ __forceinline__ void fma2(ull& d, ull a, ull b) {
    asm("fma.rn.f32x2 %0, %1, %2, %0;" : "+l"(d) : "l"(a), "l"(b));
}
__device__ __forceinline__ void add2(ull& d, ull a) {
    asm("add.rn.f32x2 %0, %0, %1;" : "+l"(d) : "l"(a));
}
__device__ __forceinline__ ull splat2(float w) {
    ull r; unsigned u = __float_as_uint(w);
    asm("mov.b64 %0, {%1, %1};" : "=l"(r) : "r"(u));
    return r;
}
__device__ __forceinline__ ull pack2(float a, float b) {
    ull r;
    asm("mov.b64 %0, {%1, %2};" : "=l"(r) : "r"(__float_as_uint(a)), "r"(__float_as_uint(b)));
    return r;
}
__device__ __forceinline__ float2 u2f2(ull v) {
    float2 f;
    f.x = __uint_as_float((unsigned)v);
    f.y = __uint_as_float((unsigned)(v >> 32));
    return f;
}
__device__ __forceinline__ void cpa16(void* dst, const void* src) {
    unsigned d = (unsigned)__cvta_generic_to_shared(dst);
    asm volatile("cp.async.cg.shared.global [%0], [%1], 16;" :: "r"(d), "l"(src));
}
__device__ __forceinline__ int warp_incl_scan(int v) {
    int lane = threadIdx.x & 31;
#pragma unroll
    for (int d = 1; d < 32; d <<= 1) {
        int t = __shfl_up_sync(0xffffffffu, v, d);
        if (lane >= d) v += t;
    }
    return v;
}
__device__ __forceinline__ float sigm(float x) { return __fdividef(1.f, 1.f + __expf(-x)); }
__device__ __forceinline__ float tanha(float x) { return 1.f - __fdividef(2.f, __expf(2.f * x) + 1.f); }

// ---------------- K1: merged prep (small proj + fused weight) ----------------
__global__ void prep_kernel(const float* __restrict__ obs,
                            const float* __restrict__ W_in,
                            const float* __restrict__ b_in,
                            const float* __restrict__ W_msg,
                            const float* __restrict__ W_gate,
                            const float* __restrict__ W_cand,
                            const int* __restrict__ afferent_idx) {
    if (blockIdx.x == 128) {
        __shared__ float proj[NB * HH];
        int t = threadIdx.x;            // 128 threads
        int b = t >> 6, h = t & 63;
        float acc = b_in[h];
        for (int o = 0; o < NOBS; o++)
            acc += obs[b * NOBS + o] * W_in[o * HH + h];
        proj[b * HH + h] = acc;
        __syncthreads();
        float ag = 0.f, ac = 0.f;
        for (int k = 0; k < HH; k++) {
            float p = proj[b * HH + k];
            ag += p * W_gate[(HH + k) * HH + h];
            ac += p * W_cand[(HH + k) * HH + h];
        }
        g_projG[b * HH + h] = ag;
        g_projC[b * HH + h] = ac;
        for (int i = t; i < NAFF; i += 128)
            g_flag[afferent_idx[i]] = 1;
    } else {
        int c = blockIdx.x;     // output column 0..127
        int k = threadIdx.x;    // input row 0..127
        float w;
        if (k < HH) {
            w = (c < HH) ? W_gate[k * HH + c] : W_cand[k * HH + (c - HH)];
        } else {
            int km = k - HH;
            float acc = 0.f;
            if (c < HH) {
                for (int t = 0; t < HH; t++)
                    acc += W_msg[km * HH + t] * W_gate[(HH + t) * HH + c];
            } else {
                for (int t = 0; t < HH; t++)
                    acc += W_msg[km * HH + t] * W_cand[(HH + t) * HH + (c - HH)];
            }
            w = acc;
        }
        g_Wp[k * 128 + c] = w;
    }
}

// ---------------- CSR build ----------------
__global__ void hist_kernel(const int4* __restrict__ dst4) {
    int i = (blockIdx.x * blockDim.x + threadIdx.x) * 2;
    if (i < NE / 4) {
        int4 d0 = __ldg(dst4 + i);
        int4 d1 = __ldg(dst4 + i + 1);
        atomicAdd(&g_cnt[d0.x], 1);
        atomicAdd(&g_cnt[d0.y], 1);
        atomicAdd(&g_cnt[d0.z], 1);
        atomicAdd(&g_cnt[d0.w], 1);
        atomicAdd(&g_cnt[d1.x], 1);
        atomicAdd(&g_cnt[d1.y], 1);
        atomicAdd(&g_cnt[d1.z], 1);
        atomicAdd(&g_cnt[d1.w], 1);
    }
}

__global__ void scan_part_kernel() {
    int i = blockIdx.x * 256 + threadIdx.x;
    int v = (i < NN) ? g_cnt[i] : 0;
    __shared__ int ws[8];
    int s = v;
#pragma unroll
    for (int d = 16; d > 0; d >>= 1) s += __shfl_down_sync(0xffffffffu, s, d);
    if ((threadIdx.x & 31) == 0) ws[threadIdx.x >> 5] = s;
    __syncthreads();
    if (threadIdx.x == 0) {
        int tot = 0;
        for (int w = 0; w < 8; w++) tot += ws[w];
        g_part[blockIdx.x] = tot;
    }
}

__global__ void scan_final_kernel() {      // grid PB, 256 thr; folds mid-scan in
    int i = blockIdx.x * 256 + threadIdx.x;
    int t = threadIdx.x;
    int lane = t & 31, w = t >> 5;
    __shared__ int ws[8];
    __shared__ int blockBase;

    // block base = sum of g_part[j] for j < blockIdx.x
    int pv = (t < PB && t < blockIdx.x) ? g_part[t] : 0;
#pragma unroll
    for (int d = 16; d > 0; d >>= 1) pv += __shfl_down_sync(0xffffffffu, pv, d);
    if (lane == 0) ws[w] = pv;
    __syncthreads();
    if (t == 0) {
        int s = 0;
        for (int x = 0; x < 8; x++) s += ws[x];
        blockBase = s;
    }
    __syncthreads();

    int v = (i < NN) ? g_cnt[i] : 0;
    int inc = warp_incl_scan(v);
    if (lane == 31) ws[w] = inc;
    __syncthreads();
    if (w == 0) {
        int q = (lane < 8) ? ws[lane] : 0;
        int qi = warp_incl_scan(q);
        if (lane < 8) ws[lane] = qi;
    }
    __syncthreads();
    int base = (w > 0) ? ws[w - 1] : 0;
    int off = blockBase + base + inc - v;
    if (i < NN) { g_off[i] = off; g_cur[i] = off; }
    if (i == 0) g_off[NN] = NE;
}

__global__ void scatter_kernel(const int4* __restrict__ src4,
                               const int4* __restrict__ dst4) {
    int i = (blockIdx.x * blockDim.x + threadIdx.x) * 2;
    if (i < NE / 4) {
        int4 s0 = __ldg(src4 + i);
        int4 d0 = __ldg(dst4 + i);
        int4 s1 = __ldg(src4 + i + 1);
        int4 d1 = __ldg(dst4 + i + 1);
        g_esrc[atomicAdd(&g_cur[d0.x], 1)] = s0.x;
        g_esrc[atomicAdd(&g_cur[d0.y], 1)] = s0.y;
        g_esrc[atomicAdd(&g_cur[d0.z], 1)] = s0.z;
        g_esrc[atomicAdd(&g_cur[d0.w], 1)] = s0.w;
        g_esrc[atomicAdd(&g_cur[d1.x], 1)] = s1.x;
        g_esrc[atomicAdd(&g_cur[d1.y], 1)] = s1.y;
        g_esrc[atomicAdd(&g_cur[d1.z], 1)] = s1.z;
        g_esrc[atomicAdd(&g_cur[d1.w], 1)] = s1.w;
    }
}

// ---------------- K2: fused gather + f32x2 GEMM + GRU epilogue ----------------
// 16 warps/block, 1 block/SM, no block syncs in the loop. Contiguous per-warp
// chunks keep the CSR slab in one smem window; gather accumulates with
// add.rn.f32x2 on raw 8-byte row loads (2 instrs/edge); FMA phase is the
// proven batch-paired f32x2 tile (splat MOVs dual-issue on alu pipe).
__global__ void __launch_bounds__(512, 1) fused_kernel(const float* __restrict__ state,
                                                       const float* __restrict__ b_gate,
                                                       const float* __restrict__ b_cand,
                                                       float* __restrict__ out_ns) {
    extern __shared__ float smem[];
    float* Ws = smem;                                    // 16384 floats
    ull* xs = (ull*)(smem + 16384);                      // NW * GROUP * 128 ull
    int* sIdx = (int*)(xs + NW * GROUP * 128);           // NW * WIN ints

    int tid = threadIdx.x;
    for (int i = tid; i < 4096; i += 512)
        ((float4*)Ws)[i] = ((const float4*)g_Wp)[i];
    __syncthreads();

    int warp = tid >> 5, lane = tid & 31;
    int q = lane & 15;
    int cc0 = q * 4;
    bool zside = lane < 16;

    float bias[4], pj0[4], pj1[4];
#pragma unroll
    for (int c = 0; c < 4; c++) {
        int cc = cc0 + c;
        if (zside) { bias[c] = __ldg(b_gate + cc); pj0[c] = g_projG[cc]; pj1[c] = g_projG[64 + cc]; }
        else       { bias[c] = __ldg(b_cand + cc); pj0[c] = g_projC[cc]; pj1[c] = g_projC[64 + cc]; }
    }

    ull* mx = xs + warp * (GROUP * 128);
    int* widx = sIdx + warp * WIN;
    int gwid = blockIdx.x * NW + warp;
    const ull* s0u = (const ull*)state;                  // row float2 == ull
    const ull* s1u = s0u + (size_t)NN * 32;

    int cBase, cCnt;
    if (gwid < NBIG) { cBase = gwid * CHUNK_BIG; cCnt = CHUNK_BIG; }
    else             { cBase = NBIG * CHUNK_BIG + (gwid - NBIG) * CHUNK_SMALL; cCnt = CHUNK_SMALL; }
    int nEnd = cBase + cCnt;

    // stage index window for the chunk
    int slab = __ldg(&g_off[cBase]) & ~3;
    for (int c = lane; c < WIN / 4; c += 32)
        cpa16(widx + c * 4, g_esrc + slab + c * 4);
    asm volatile("cp.async.commit_group;" ::: "memory");
    asm volatile("cp.async.wait_group 0;" ::: "memory");
    __syncwarp();

    int sg = 1 + (gwid % GROUP);       // staggered first sub-group size
    int n0 = cBase;
    while (n0 < nEnd) {
        int cnt = nEnd - n0;
        if (cnt > sg) cnt = sg;
        sg = GROUP;
        int flg[GROUP];

        // ---- gather phase (ull loads + f32x2 accumulate) ----
        for (int m = 0; m < cnt; m++) {
            int n = n0 + m;
            int beg = __ldg(&g_off[n]), end = __ldg(&g_off[n + 1]);
            flg[m] = __ldg(&g_flag[n]);
            ull accA = 0ull, accB = 0ull;     // (b0 k2l, b0 k2l+1), (b1 ...)
            int j = beg;
            while (j < end) {
                if (j >= slab + WIN) {           // refill window (rare)
                    slab = j & ~3;
                    for (int c = lane; c < WIN / 4; c += 32)
                        cpa16(widx + c * 4, g_esrc + slab + c * 4);
                    asm volatile("cp.async.commit_group;" ::: "memory");
                    asm volatile("cp.async.wait_group 0;" ::: "memory");
                    __syncwarp();
                }
                int lim = slab + WIN;
                if (lim > end) lim = end;
                for (; j + 8 <= lim; j += 8) {
                    int e[8];
#pragma unroll
                    for (int u = 0; u < 8; u++) e[u] = widx[j - slab + u];
                    ull av[8], bv[8];
#pragma unroll
                    for (int u = 0; u < 8; u++) {
                        av[u] = __ldg(s0u + (size_t)e[u] * 32 + lane);
                        bv[u] = __ldg(s1u + (size_t)e[u] * 32 + lane);
                    }
#pragma unroll
                    for (int u = 0; u < 8; u++) {
                        add2(accA, av[u]);
                        add2(accB, bv[u]);
                    }
                }
                for (; j < lim; j++) {
                    int e0 = widx[j - slab];
                    add2(accA, __ldg(s0u + (size_t)e0 * 32 + lane));
                    add2(accB, __ldg(s1u + (size_t)e0 * 32 + lane));
                }
            }
            float2 sa = u2f2(__ldg(s0u + (size_t)n * 32 + lane));
            float2 sb = u2f2(__ldg(s1u + (size_t)n * 32 + lane));
            float2 aA = u2f2(accA), aB = u2f2(accB);
            ull* row = mx + m * 128;
            // batch-pair interleave: state half (k=2l,2l+1), agg half (k=64+2l,...)
            ((float4*)row)[lane]        = make_float4(sa.x, sb.x, sa.y, sb.y);
            ((float4*)(row + 64))[lane] = make_float4(aA.x, aB.x, aA.y, aB.y);
        }
        __syncwarp();

        // ---- FMA phase (batch-paired, splat weights) ----
        ull acc6[GROUP][4];
#pragma unroll
        for (int m = 0; m < GROUP; m++)
#pragma unroll
            for (int c = 0; c < 4; c++) acc6[m][c] = 0ull;

#pragma unroll 4
        for (int k = 0; k < 128; k += 2) {
            float4 wA = ((const float4*)(Ws + k * 128))[lane];
            float4 wB = ((const float4*)(Ws + (k + 1) * 128))[lane];
            ull wa0 = splat2(wA.x), wa1 = splat2(wA.y), wa2 = splat2(wA.z), wa3 = splat2(wA.w);
            ull wb0 = splat2(wB.x), wb1 = splat2(wB.y), wb2 = splat2(wB.z), wb3 = splat2(wB.w);
#pragma unroll
            for (int m = 0; m < GROUP; m++) {
                ulonglong2 xv = ((const ulonglong2*)(mx + m * 128))[k >> 1];
                fma2(acc6[m][0], wa0, xv.x); fma2(acc6[m][1], wa1, xv.x);
                fma2(acc6[m][2], wa2, xv.x); fma2(acc6[m][3], wa3, xv.x);
                fma2(acc6[m][0], wb0, xv.y); fma2(acc6[m][1], wb1, xv.y);
                fma2(acc6[m][2], wb2, xv.y); fma2(acc6[m][3], wb3, xv.y);
            }
        }

        // ---- epilogue ----
        for (int m = 0; m < cnt; m++) {
            int n = n0 + m;
            ull actp[4];
#pragma unroll
            for (int c = 0; c < 4; c++) {
                float2 pre = u2f2(acc6[m][c]);
                float p0 = pre.x + bias[c] + (flg[m] ? pj0[c] : 0.f);
                float p1 = pre.y + bias[c] + (flg[m] ? pj1[c] : 0.f);
                float a0, a1;
                if (zside) { a0 = sigm(p0);  a1 = sigm(p1); }
                else       { a0 = tanha(p0); a1 = tanha(p1); }
                actp[c] = pack2(a0, a1);
            }
            ull oth[4];
#pragma unroll
            for (int c = 0; c < 4; c++)
                oth[c] = __shfl_xor_sync(0xffffffffu, actp[c], 16);
            if (zside) {
                float4 r0, r1;
                float* q0 = (float*)&r0;
                float* q1 = (float*)&r1;
#pragma unroll
                for (int c = 0; c < 4; c++) {
                    float2 z = u2f2(actp[c]);
                    float2 t = u2f2(oth[c]);
                    float2 sp = u2f2(mx[m * 128 + cc0 + c]);
                    q0[c] = fmaf(z.x, t.x - sp.x, sp.x);
                    q1[c] = fmaf(z.y, t.y - sp.y, sp.y);
                }
                *((float4*)(out_ns + (size_t)n * 64 + cc0)) = r0;
                *((float4*)(out_ns + ((size_t)NN + n) * 64 + cc0)) = r1;
            }
        }
        __syncwarp();
        n0 += cnt;
    }
}

// ---------------- K4: readout + policy heads ----------------
__global__ void readout_kernel(const float* __restrict__ ns,
                               const int* __restrict__ efferent_idx,
                               const float* __restrict__ W_dec,
                               const float* __restrict__ b_dec,
                               const float* __restrict__ W_mean,
                               const float* __restrict__ b_mean,
                               const float* __restrict__ W_ls,
                               const float* __restrict__ b_ls,
                               float* __restrict__ out) {
    __shared__ float ro[NB * HH];
    __shared__ float dec[NB * HH];
    int t = threadIdx.x;
    int b = t >> 6, h = t & 63;
    float sum = 0.f;
    for (int i = 0; i < NEFF; i++) {
        int idx = efferent_idx[i];
        sum += ns[((size_t)b * NN + idx) * HH + h];
    }
    ro[b * HH + h] = sum * (1.f / NEFF);
    __syncthreads();
    float acc = b_dec[h];
    for (int k = 0; k < HH; k++)
        acc += ro[b * HH + k] * W_dec[k * HH + h];
    dec[b * HH + h] = tanhf(acc);
    __syncthreads();
    if (t < NB * NA) {
        int bb = t / NA, a = t % NA;
        float m = b_mean[a], ls = b_ls[a];
        for (int k = 0; k < HH; k++) {
            float d = dec[bb * HH + k];
            m  += d * W_mean[k * NA + a];
            ls += d * W_ls[k * NA + a];
        }
        ls = fminf(fmaxf(ls, -5.f), 2.f);
        out[bb * NA + a] = m;
        out[NB * NA + bb * NA + a] = ls;
    }
}

// ---------------- launch ----------------
extern "C" void kernel_launch(void* const* d_in, const int* in_sizes, int n_in,
                              void* d_out, int out_size) {
    const float* obs    = (const float*)d_in[0];
    const float* state  = (const float*)d_in[1];
    const float* W_in   = (const float*)d_in[2];
    const float* b_in   = (const float*)d_in[3];
    const float* W_msg  = (const float*)d_in[4];
    const float* W_gate = (const float*)d_in[5];
    const float* b_gate = (const float*)d_in[6];
    const float* W_cand = (const float*)d_in[7];
    const float* b_cand = (const float*)d_in[8];
    const float* W_dec  = (const float*)d_in[9];
    const float* b_dec  = (const float*)d_in[10];
    const float* W_mean = (const float*)d_in[11];
    const float* b_mean = (const float*)d_in[12];
    const float* W_ls   = (const float*)d_in[13];
    const float* b_ls   = (const float*)d_in[14];
    const int* src_idx  = (const int*)d_in[15];
    const int* dst_idx  = (const int*)d_in[16];
    const int* aff_idx  = (const int*)d_in[17];
    const int* eff_idx  = (const int*)d_in[18];
    float* out = (float*)d_out;
    float* out_ns = out + 2 * NB * NA;

    void *cntp = nullptr, *flagp = nullptr;
    cudaGetSymbolAddress(&cntp, g_cnt);
    cudaGetSymbolAddress(&flagp, g_flag);
    cudaMemsetAsync(cntp, 0, sizeof(int) * NN);
    cudaMemsetAsync(flagp, 0, sizeof(int) * NN);

    prep_kernel<<<129, 128>>>(obs, W_in, b_in, W_msg, W_gate, W_cand, aff_idx);

    hist_kernel<<<(NE / 8 + 255) / 256, 256>>>((const int4*)dst_idx);
    scan_part_kernel<<<PB, 256>>>();
    scan_final_kernel<<<PB, 256>>>();
    scatter_kernel<<<(NE / 8 + 255) / 256, 256>>>((const int4*)src_idx, (const int4*)dst_idx);

    size_t smem = 16384u * 4 + (size_t)NW * GROUP * 128 * 8 + (size_t)NW * WIN * 4;  // 196608
    cudaFuncSetAttribute(fused_kernel, cudaFuncAttributeMaxDynamicSharedMemorySize, (int)smem);
    fused_kernel<<<NBLK, 512, smem>>>(state, b_gate, b_cand, out_ns);

    readout_kernel<<<1, 128>>>(out_ns, eff_idx, W_dec, b_dec, W_mean, b_mean, W_ls, b_ls, out);
}

// round 12
// speedup vs baseline: 1.2214x; 1.0120x over previous
#include <cuda_runtime.h>
#include <cstdint>
#include <cstdio>

#define NB   2
#define NN   50000
#define HH   64
#define NE   1000000
#define NOBS 128
#define NA   18
#define NAFF 512
#define NEFF 256
#define PB   196

#define NBLK   148
#define NW     16
#define WTOT   (NBLK * NW)     // 2368 warps
#define GROUP  6
#define WIN    512             // idx window (ints) per warp

// chunk split: NN = WTOT*21 + 272  ->  first 272 warps take 22 nodes
#define CHUNK_BIG   22
#define CHUNK_SMALL 21
#define NBIG        (NN - WTOT * CHUNK_SMALL)   // 272

typedef unsigned int u32;
typedef unsigned long long ull;

// ---------------- device scratch ----------------
__device__ float g_Wp[128 * 128];             // fused weight [k][c]
__device__ float g_projG[NB * HH];
__device__ float g_projC[NB * HH];
__device__ int   g_flag[NN];
__device__ int   g_cnt[NN];
__device__ int   g_off[NN + 1];
__device__ int   g_cur[NN];
__device__ int   g_esrc[NE + WIN];            // padded for cp.async overread
__device__ int   g_part[256];

// ---------------- helpers ----------------
__device__ __forceinline__ void fma2(ull& d, ull a, ull b) {
    asm("fma.rn.f32x2 %0, %1, %2, %0;" : "+l"(d) : "l"(a), "l"(b));
}
__device__ __forceinline__ void add2(ull& d, ull a) {
    asm("add.rn.f32x2 %0, %0, %1;" : "+l"(d) : "l"(a));
}
__device__ __forceinline__ ull splat2(float w) {
    ull r; unsigned u = __float_as_uint(w);
    asm("mov.b64 %0, {%1, %1};" : "=l"(r) : "r"(u));
    return r;
}
__device__ __forceinline__ ull pack2(float a, float b) {
    ull r;
    asm("mov.b64 %0, {%1, %2};" : "=l"(r) : "r"(__float_as_uint(a)), "r"(__float_as_uint(b)));
    return r;
}
__device__ __forceinline__ float2 u2f2(ull v) {
    float2 f;
    f.x = __uint_as_float((unsigned)v);
    f.y = __uint_as_float((unsigned)(v >> 32));
    return f;
}
__device__ __forceinline__ void cpa16(void* dst, const void* src) {
    unsigned d = (unsigned)__cvta_generic_to_shared(dst);
    asm volatile("cp.async.cg.shared.global [%0], [%1], 16;" :: "r"(d), "l"(src));
}
__device__ __forceinline__ int warp_incl_scan(int v) {
    int lane = threadIdx.x & 31;
#pragma unroll
    for (int d = 1; d < 32; d <<= 1) {
        int t = __shfl_up_sync(0xffffffffu, v, d);
        if (lane >= d) v += t;
    }
    return v;
}
__device__ __forceinline__ float sigm(float x) { return __fdividef(1.f, 1.f + __expf(-x)); }
__device__ __forceinline__ float tanha(float x) { return 1.f - __fdividef(2.f, __expf(2.f * x) + 1.f); }

// ---------------- K1: merged prep (proj + flags + fused weight + cnt zero) ----------------
__global__ void prep_kernel(const float* __restrict__ obs,
                            const float* __restrict__ W_in,
                            const float* __restrict__ b_in,
                            const float* __restrict__ W_msg,
                            const float* __restrict__ W_gate,
                            const float* __restrict__ W_cand,
                            const int* __restrict__ afferent_idx) {
    if (blockIdx.x == 128) {
        // zero flags first, then projections + flag set
        int t = threadIdx.x;
        int4 z4 = make_int4(0, 0, 0, 0);
        for (int i = t; i < NN / 4; i += 128)
            ((int4*)g_flag)[i] = z4;
        __syncthreads();
        __shared__ float proj[NB * HH];
        int b = t >> 6, h = t & 63;
        float acc = b_in[h];
        for (int o = 0; o < NOBS; o++)
            acc += obs[b * NOBS + o] * W_in[o * HH + h];
        proj[b * HH + h] = acc;
        __syncthreads();
        float ag = 0.f, ac = 0.f;
        for (int k = 0; k < HH; k++) {
            float p = proj[b * HH + k];
            ag += p * W_gate[(HH + k) * HH + h];
            ac += p * W_cand[(HH + k) * HH + h];
        }
        g_projG[b * HH + h] = ag;
        g_projC[b * HH + h] = ac;
        for (int i = t; i < NAFF; i += 128)
            g_flag[afferent_idx[i]] = 1;
    } else {
        // zero a slice of g_cnt
        const int per = (NN + 127) / 128;   // 391
        int s = blockIdx.x * per;
        int e = s + per; if (e > NN) e = NN;
        for (int i = s + threadIdx.x; i < e; i += 128)
            g_cnt[i] = 0;
        // fused weight column
        int c = blockIdx.x;     // output column 0..127
        int k = threadIdx.x;    // input row 0..127
        float w;
        if (k < HH) {
            w = (c < HH) ? W_gate[k * HH + c] : W_cand[k * HH + (c - HH)];
        } else {
            int km = k - HH;
            float acc = 0.f;
            if (c < HH) {
                for (int t2 = 0; t2 < HH; t2++)
                    acc += W_msg[km * HH + t2] * W_gate[(HH + t2) * HH + c];
            } else {
                for (int t2 = 0; t2 < HH; t2++)
                    acc += W_msg[km * HH + t2] * W_cand[(HH + t2) * HH + (c - HH)];
            }
            w = acc;
        }
        g_Wp[k * 128 + c] = w;
    }
}

// ---------------- CSR build ----------------
__global__ void hist_kernel(const int4* __restrict__ dst4) {
    int i = (blockIdx.x * blockDim.x + threadIdx.x) * 2;
    if (i < NE / 4) {
        int4 d0 = __ldg(dst4 + i);
        int4 d1 = __ldg(dst4 + i + 1);
        atomicAdd(&g_cnt[d0.x], 1);
        atomicAdd(&g_cnt[d0.y], 1);
        atomicAdd(&g_cnt[d0.z], 1);
        atomicAdd(&g_cnt[d0.w], 1);
        atomicAdd(&g_cnt[d1.x], 1);
        atomicAdd(&g_cnt[d1.y], 1);
        atomicAdd(&g_cnt[d1.z], 1);
        atomicAdd(&g_cnt[d1.w], 1);
    }
}

__global__ void scan_part_kernel() {
    int i = blockIdx.x * 256 + threadIdx.x;
    int v = (i < NN) ? g_cnt[i] : 0;
    __shared__ int ws[8];
    int s = v;
#pragma unroll
    for (int d = 16; d > 0; d >>= 1) s += __shfl_down_sync(0xffffffffu, s, d);
    if ((threadIdx.x & 31) == 0) ws[threadIdx.x >> 5] = s;
    __syncthreads();
    if (threadIdx.x == 0) {
        int tot = 0;
        for (int w = 0; w < 8; w++) tot += ws[w];
        g_part[blockIdx.x] = tot;
    }
}

__global__ void scan_final_kernel() {      // grid PB, 256 thr; folds mid-scan in
    int i = blockIdx.x * 256 + threadIdx.x;
    int t = threadIdx.x;
    int lane = t & 31, w = t >> 5;
    __shared__ int ws[8];
    __shared__ int blockBase;

    int pv = (t < PB && t < blockIdx.x) ? g_part[t] : 0;
#pragma unroll
    for (int d = 16; d > 0; d >>= 1) pv += __shfl_down_sync(0xffffffffu, pv, d);
    if (lane == 0) ws[w] = pv;
    __syncthreads();
    if (t == 0) {
        int s = 0;
        for (int x = 0; x < 8; x++) s += ws[x];
        blockBase = s;
    }
    __syncthreads();

    int v = (i < NN) ? g_cnt[i] : 0;
    int inc = warp_incl_scan(v);
    if (lane == 31) ws[w] = inc;
    __syncthreads();
    if (w == 0) {
        int q = (lane < 8) ? ws[lane] : 0;
        int qi = warp_incl_scan(q);
        if (lane < 8) ws[lane] = qi;
    }
    __syncthreads();
    int base = (w > 0) ? ws[w - 1] : 0;
    int off = blockBase + base + inc - v;
    if (i < NN) { g_off[i] = off; g_cur[i] = off; }
    if (i == 0) g_off[NN] = NE;
}

__global__ void scatter_kernel(const int4* __restrict__ src4,
                               const int4* __restrict__ dst4) {
    int i = (blockIdx.x * blockDim.x + threadIdx.x) * 2;
    if (i < NE / 4) {
        int4 s0 = __ldg(src4 + i);
        int4 d0 = __ldg(dst4 + i);
        int4 s1 = __ldg(src4 + i + 1);
        int4 d1 = __ldg(dst4 + i + 1);
        g_esrc[atomicAdd(&g_cur[d0.x], 1)] = s0.x;
        g_esrc[atomicAdd(&g_cur[d0.y], 1)] = s0.y;
        g_esrc[atomicAdd(&g_cur[d0.z], 1)] = s0.z;
        g_esrc[atomicAdd(&g_cur[d0.w], 1)] = s0.w;
        g_esrc[atomicAdd(&g_cur[d1.x], 1)] = s1.x;
        g_esrc[atomicAdd(&g_cur[d1.y], 1)] = s1.y;
        g_esrc[atomicAdd(&g_cur[d1.z], 1)] = s1.z;
        g_esrc[atomicAdd(&g_cur[d1.w], 1)] = s1.w;
    }
}

// ---------------- K2: fused gather + f32x2 GEMM + GRU epilogue ----------------
// Gather: split-batch LDG.128 (lane<16 loads b0 float4 chunk, lane>=16 b1);
// 1 load/edge/warp. One shfl exchange per NODE rebuilds the batch-interleaved
// smem row. FMA phase: proven batch-paired f32x2 tile.
__global__ void __launch_bounds__(512, 1) fused_kernel(const float* __restrict__ state,
                                                       const float* __restrict__ b_gate,
                                                       const float* __restrict__ b_cand,
                                                       float* __restrict__ out_ns) {
    extern __shared__ float smem[];
    float* Ws = smem;                                    // 16384 floats
    ull* xs = (ull*)(smem + 16384);                      // NW * GROUP * 128 ull
    int* sIdx = (int*)(xs + NW * GROUP * 128);           // NW * WIN ints

    int tid = threadIdx.x;
    for (int i = tid; i < 4096; i += 512)
        ((float4*)Ws)[i] = ((const float4*)g_Wp)[i];
    __syncthreads();

    int warp = tid >> 5, lane = tid & 31;
    int q = lane & 15;
    int cc0 = q * 4;
    bool zside = lane < 16;
    int l4 = lane & 15;
    int half = lane >> 4;      // 0: batch0, 1: batch1

    float bias[4], pj0[4], pj1[4];
#pragma unroll
    for (int c = 0; c < 4; c++) {
        int cc = cc0 + c;
        if (zside) { bias[c] = __ldg(b_gate + cc); pj0[c] = g_projG[cc]; pj1[c] = g_projG[64 + cc]; }
        else       { bias[c] = __ldg(b_cand + cc); pj0[c] = g_projC[cc]; pj1[c] = g_projC[64 + cc]; }
    }

    ull* mx = xs + warp * (GROUP * 128);
    int* widx = sIdx + warp * WIN;
    int gwid = blockIdx.x * NW + warp;
    // split-batch view: node n, chunk l4 (16B) of this lane's batch
    const ulonglong2* U2 = (const ulonglong2*)state + (size_t)half * NN * 16;

    int cBase, cCnt;
    if (gwid < NBIG) { cBase = gwid * CHUNK_BIG; cCnt = CHUNK_BIG; }
    else             { cBase = NBIG * CHUNK_BIG + (gwid - NBIG) * CHUNK_SMALL; cCnt = CHUNK_SMALL; }
    int nEnd = cBase + cCnt;

    // stage index window for the chunk
    int slab = __ldg(&g_off[cBase]) & ~3;
    for (int c = lane; c < WIN / 4; c += 32)
        cpa16(widx + c * 4, g_esrc + slab + c * 4);
    asm volatile("cp.async.commit_group;" ::: "memory");
    asm volatile("cp.async.wait_group 0;" ::: "memory");
    __syncwarp();

    int sg = 1 + (gwid % GROUP);       // staggered first sub-group size
    int n0 = cBase;
    while (n0 < nEnd) {
        int cnt = nEnd - n0;
        if (cnt > sg) cnt = sg;
        sg = GROUP;
        int flg[GROUP];

        // ---- gather phase (split-batch LDG.128 + f32x2 accumulate) ----
        for (int m = 0; m < cnt; m++) {
            int n = n0 + m;
            int beg = __ldg(&g_off[n]), end = __ldg(&g_off[n + 1]);
            flg[m] = __ldg(&g_flag[n]);
            ull a0 = 0ull, a1 = 0ull;      // this batch: floats 4l4..4l4+1, 4l4+2..+3
            int j = beg;
            while (j < end) {
                if (j >= slab + WIN) {           // refill window (rare)
                    slab = j & ~3;
                    for (int c = lane; c < WIN / 4; c += 32)
                        cpa16(widx + c * 4, g_esrc + slab + c * 4);
                    asm volatile("cp.async.commit_group;" ::: "memory");
                    asm volatile("cp.async.wait_group 0;" ::: "memory");
                    __syncwarp();
                }
                int lim = slab + WIN;
                if (lim > end) lim = end;
                for (; j + 8 <= lim; j += 8) {
                    int e[8];
#pragma unroll
                    for (int u = 0; u < 8; u++) e[u] = widx[j - slab + u];
                    ulonglong2 v[8];
#pragma unroll
                    for (int u = 0; u < 8; u++)
                        v[u] = __ldg(U2 + (size_t)e[u] * 16 + l4);
#pragma unroll
                    for (int u = 0; u < 8; u++) {
                        add2(a0, v[u].x);
                        add2(a1, v[u].y);
                    }
                }
                for (; j < lim; j++) {
                    int e0 = widx[j - slab];
                    ulonglong2 v0 = __ldg(U2 + (size_t)e0 * 16 + l4);
                    add2(a0, v0.x);
                    add2(a1, v0.y);
                }
            }
            ulonglong2 so = __ldg(U2 + (size_t)n * 16 + l4);   // own state chunk
            // exchange with partner lane (other batch)
            ull po0 = __shfl_xor_sync(0xffffffffu, so.x, 16);
            ull po1 = __shfl_xor_sync(0xffffffffu, so.y, 16);
            ull qa0 = __shfl_xor_sync(0xffffffffu, a0, 16);
            ull qa1 = __shfl_xor_sync(0xffffffffu, a1, 16);
            ull* row = mx + m * 128;
            if (lane < 16) {
                // state entries k=4l4..4l4+3: {b0[k], b1[k]} pairs
                float2 o0 = u2f2(so.x), o1 = u2f2(so.y);   // b0
                float2 p0 = u2f2(po0),  p1 = u2f2(po1);    // b1
                ((float4*)row)[2 * l4]     = make_float4(o0.x, p0.x, o0.y, p0.y);
                ((float4*)row)[2 * l4 + 1] = make_float4(o1.x, p1.x, o1.y, p1.y);
            } else {
                // agg entries: own = b1 agg, partner = b0 agg
                float2 o0 = u2f2(a0),  o1 = u2f2(a1);      // b1
                float2 p0 = u2f2(qa0), p1 = u2f2(qa1);     // b0
                ((float4*)(row + 64))[2 * l4]     = make_float4(p0.x, o0.x, p0.y, o0.y);
                ((float4*)(row + 64))[2 * l4 + 1] = make_float4(p1.x, o1.x, p1.y, o1.y);
            }
        }
        __syncwarp();

        // ---- FMA phase (batch-paired, splat weights) ----
        ull acc6[GROUP][4];
#pragma unroll
        for (int m = 0; m < GROUP; m++)
#pragma unroll
            for (int c = 0; c < 4; c++) acc6[m][c] = 0ull;

#pragma unroll 4
        for (int k = 0; k < 128; k += 2) {
            float4 wA = ((const float4*)(Ws + k * 128))[lane];
            float4 wB = ((const float4*)(Ws + (k + 1) * 128))[lane];
            ull wa0 = splat2(wA.x), wa1 = splat2(wA.y), wa2 = splat2(wA.z), wa3 = splat2(wA.w);
            ull wb0 = splat2(wB.x), wb1 = splat2(wB.y), wb2 = splat2(wB.z), wb3 = splat2(wB.w);
#pragma unroll
            for (int m = 0; m < GROUP; m++) {
                ulonglong2 xv = ((const ulonglong2*)(mx + m * 128))[k >> 1];
                fma2(acc6[m][0], wa0, xv.x); fma2(acc6[m][1], wa1, xv.x);
                fma2(acc6[m][2], wa2, xv.x); fma2(acc6[m][3], wa3, xv.x);
                fma2(acc6[m][0], wb0, xv.y); fma2(acc6[m][1], wb1, xv.y);
                fma2(acc6[m][2], wb2, xv.y); fma2(acc6[m][3], wb3, xv.y);
            }
        }

        // ---- epilogue ----
        for (int m = 0; m < cnt; m++) {
            int n = n0 + m;
            ull actp[4];
#pragma unroll
            for (int c = 0; c < 4; c++) {
                float2 pre = u2f2(acc6[m][c]);
                float p0 = pre.x + bias[c] + (flg[m] ? pj0[c] : 0.f);
                float p1 = pre.y + bias[c] + (flg[m] ? pj1[c] : 0.f);
                float a0f, a1f;
                if (zside) { a0f = sigm(p0);  a1f = sigm(p1); }
                else       { a0f = tanha(p0); a1f = tanha(p1); }
                actp[c] = pack2(a0f, a1f);
            }
            ull oth[4];
#pragma unroll
            for (int c = 0; c < 4; c++)
                oth[c] = __shfl_xor_sync(0xffffffffu, actp[c], 16);
            if (zside) {
                float4 r0, r1;
                float* q0 = (float*)&r0;
                float* q1 = (float*)&r1;
#pragma unroll
                for (int c = 0; c < 4; c++) {
                    float2 z = u2f2(actp[c]);
                    float2 t = u2f2(oth[c]);
                    float2 sp = u2f2(mx[m * 128 + cc0 + c]);
                    q0[c] = fmaf(z.x, t.x - sp.x, sp.x);
                    q1[c] = fmaf(z.y, t.y - sp.y, sp.y);
                }
                *((float4*)(out_ns + (size_t)n * 64 + cc0)) = r0;
                *((float4*)(out_ns + ((size_t)NN + n) * 64 + cc0)) = r1;
            }
        }
        __syncwarp();
        n0 += cnt;
    }
}

// ---------------- K4: readout + policy heads ----------------
__global__ void readout_kernel(const float* __restrict__ ns,
                               const int* __restrict__ efferent_idx,
                               const float* __restrict__ W_dec,
                               const float* __restrict__ b_dec,
                               const float* __restrict__ W_mean,
                               const float* __restrict__ b_mean,
                               const float* __restrict__ W_ls,
                               const float* __restrict__ b_ls,
                               float* __restrict__ out) {
    __shared__ float ro[NB * HH];
    __shared__ float dec[NB * HH];
    int t = threadIdx.x;
    int b = t >> 6, h = t & 63;
    float sum = 0.f;
    for (int i = 0; i < NEFF; i++) {
        int idx = efferent_idx[i];
        sum += ns[((size_t)b * NN + idx) * HH + h];
    }
    ro[b * HH + h] = sum * (1.f / NEFF);
    __syncthreads();
    float acc = b_dec[h];
    for (int k = 0; k < HH; k++)
        acc += ro[b * HH + k] * W_dec[k * HH + h];
    dec[b * HH + h] = tanhf(acc);
    __syncthreads();
    if (t < NB * NA) {
        int bb = t / NA, a = t % NA;
        float m = b_mean[a], ls = b_ls[a];
        for (int k = 0; k < HH; k++) {
            float d = dec[bb * HH + k];
            m  += d * W_mean[k * NA + a];
            ls += d * W_ls[k * NA + a];
        }
        ls = fminf(fmaxf(ls, -5.f), 2.f);
        out[bb * NA + a] = m;
        out[NB * NA + bb * NA + a] = ls;
    }
}

// ---------------- launch ----------------
extern "C" void kernel_launch(void* const* d_in, const int* in_sizes, int n_in,
                              void* d_out, int out_size) {
    const float* obs    = (const float*)d_in[0];
    const float* state  = (const float*)d_in[1];
    const float* W_in   = (const float*)d_in[2];
    const float* b_in   = (const float*)d_in[3];
    const float* W_msg  = (const float*)d_in[4];
    const float* W_gate = (const float*)d_in[5];
    const float* b_gate = (const float*)d_in[6];
    const float* W_cand = (const float*)d_in[7];
    const float* b_cand = (const float*)d_in[8];
    const float* W_dec  = (const float*)d_in[9];
    const float* b_dec  = (const float*)d_in[10];
    const float* W_mean = (const float*)d_in[11];
    const float* b_mean = (const float*)d_in[12];
    const float* W_ls   = (const float*)d_in[13];
    const float* b_ls   = (const float*)d_in[14];
    const int* src_idx  = (const int*)d_in[15];
    const int* dst_idx  = (const int*)d_in[16];
    const int* aff_idx  = (const int*)d_in[17];
    const int* eff_idx  = (const int*)d_in[18];
    float* out = (float*)d_out;
    float* out_ns = out + 2 * NB * NA;

    prep_kernel<<<129, 128>>>(obs, W_in, b_in, W_msg, W_gate, W_cand, aff_idx);

    hist_kernel<<<(NE / 8 + 255) / 256, 256>>>((const int4*)dst_idx);
    scan_part_kernel<<<PB, 256>>>();
    scan_final_kernel<<<PB, 256>>>();
    scatter_kernel<<<(NE / 8 + 255) / 256, 256>>>((const int4*)src_idx, (const int4*)dst_idx);

    size_t smem = 16384u * 4 + (size_t)NW * GROUP * 128 * 8 + (size_t)NW * WIN * 4;  // 196608
    cudaFuncSetAttribute(fused_kernel, cudaFuncAttributeMaxDynamicSharedMemorySize, (int)smem);
    fused_kernel<<<NBLK, 512, smem>>>(state, b_gate, b_cand, out_ns);

    readout_kernel<<<1, 128>>>(out_ns, eff_idx, W_dec, b_dec, W_mean, b_mean, W_ls, b_ls, out);
}